// round 3
// baseline (speedup 1.0000x reference)
#include <cuda_runtime.h>
#include <cstdint>

// Problem constants (shapes fixed by the dataset)
#define K_DIM 256
#define C_DIM 64
#define MAX_N 100000
#define MAX_E 3200000

// Scratch (no allocations allowed -> __device__ globals)
__device__ float4 g_h[(size_t)MAX_N * 16];     // g = dis[row] * (x @ W)  [N,64], 16B aligned
__device__ float  g_deg[MAX_N];                // degree incl. self loop
__device__ float  g_dis[MAX_N];                // deg^{-1/2}
__device__ int    g_is64;                      // edge_index dtype flag (1 = int64, 0 = int32)

// ---------------------------------------------------------------------------
// f32x2 packed-FMA helpers (Blackwell fma.rn.f32x2: 2x fp32 FMA throughput)
// ---------------------------------------------------------------------------
__device__ __forceinline__ unsigned long long pack2(float lo, float hi) {
    unsigned long long r;
    asm("mov.b64 %0, {%1, %2};" : "=l"(r) : "f"(lo), "f"(hi));
    return r;
}
__device__ __forceinline__ void unpack2(unsigned long long v, float& lo, float& hi) {
    asm("mov.b64 {%0, %1}, %2;" : "=f"(lo), "=f"(hi) : "l"(v));
}
__device__ __forceinline__ void fma2(unsigned long long& d, unsigned long long a,
                                     unsigned long long b) {
    asm("fma.rn.f32x2 %0, %1, %2, %0;" : "+l"(d) : "l"(a), "l"(b));
}

// ---------------------------------------------------------------------------
// K0: zero out accumulator (d_out), init deg = 1 (self loop), flag = 1
// ---------------------------------------------------------------------------
__global__ void init_kernel(float4* __restrict__ out4, int n) {
    int i = blockIdx.x * blockDim.x + threadIdx.x;
    int total4 = n * (C_DIM / 4);
    if (i < total4) out4[i] = make_float4(0.f, 0.f, 0.f, 0.f);
    if (i < n) g_deg[i] = 1.0f;
    if (i == 0) g_is64 = 1;
}

// ---------------------------------------------------------------------------
// K1: detect edge_index dtype. If the buffer is really int32, interpreting it
// as int64 aliases pairs (lo + hi*2^32); any nonzero "hi" makes the value >= N.
// ---------------------------------------------------------------------------
__global__ void detect_kernel(const long long* __restrict__ ei, int E, int n) {
    int i = blockIdx.x * blockDim.x + threadIdx.x;
    int m = E < 4096 ? E : 4096;
    if (i < m) {
        long long v = ei[i];  // always within the smaller (int32) buffer size
        if (v < 0 || v >= (long long)n) g_is64 = 0;
    }
}

__device__ __forceinline__ int edge_at(const void* ei, int is64, size_t idx) {
    return is64 ? (int)((const long long*)ei)[idx] : ((const int*)ei)[idx];
}

// ---------------------------------------------------------------------------
// K2: degree over destination nodes
// ---------------------------------------------------------------------------
__global__ void deg_kernel(const void* __restrict__ ei, int E) {
    int e = blockIdx.x * blockDim.x + threadIdx.x;
    if (e >= E) return;
    int c = edge_at(ei, g_is64, (size_t)E + e);
    atomicAdd(g_deg + c, 1.0f);
}

// ---------------------------------------------------------------------------
// K3: dis = rsqrt(deg)   (deg >= 1 always)
// ---------------------------------------------------------------------------
__global__ void dis_kernel(int n) {
    int i = blockIdx.x * blockDim.x + threadIdx.x;
    if (i < n) g_dis[i] = rsqrtf(g_deg[i]);
}

// ---------------------------------------------------------------------------
// K4: g = dis[row] * (x @ W)
// Block tile: 128 rows x 64 cols. Per thread: 8 rows x 4 cols, rows packed
// pairwise into f32x2 accumulators. W fully SMEM resident.
// ---------------------------------------------------------------------------
#define GM_TM 128
#define GM_KT 32
#define XS_STRIDE 36   // 32 + 4 pad (keeps 16B alignment, avoids conflicts)

__global__ __launch_bounds__(256) void gemm_kernel(
    const float* __restrict__ x, const float* __restrict__ W, int n) {
    extern __shared__ float smem[];
    float* Ws = smem;                       // 256*64 floats = 64KB
    float* xs = smem + K_DIM * C_DIM;       // 128*36 floats = 18KB

    int t = threadIdx.x;
    int base = blockIdx.x * GM_TM;

    // Load full W (coalesced float4)
    for (int i = t; i < (K_DIM * C_DIM) / 4; i += 256)
        ((float4*)Ws)[i] = ((const float4*)W)[i];

    int cg = t & 15;        // column group: 16 groups x 4 cols = 64
    int rg = t >> 4;        // row group:    16 groups x 8 rows = 128
    int c0 = cg * 4;
    int r0 = rg * 8;

    unsigned long long acc[4][4];  // [row-pair p][col j]; lo = row 2p, hi = row 2p+1
#pragma unroll
    for (int p = 0; p < 4; p++)
#pragma unroll
        for (int j = 0; j < 4; j++) acc[p][j] = 0ULL;

    for (int kt = 0; kt < K_DIM; kt += GM_KT) {
        __syncthreads();  // W ready (first iter) / xs reuse safe (later iters)
        // Stage x tile: 128 rows x 32 k-values, coalesced float4
        for (int i = t; i < (GM_TM * GM_KT) / 4; i += 256) {
            int row = i >> 3;            // 8 float4 per row
            int kq = i & 7;
            int grow = base + row;
            float4 v = make_float4(0.f, 0.f, 0.f, 0.f);
            if (grow < n)
                v = *(const float4*)(x + (size_t)grow * K_DIM + kt + kq * 4);
            *(float4*)(xs + row * XS_STRIDE + kq * 4) = v;
        }
        __syncthreads();

#pragma unroll
        for (int k4 = 0; k4 < GM_KT; k4 += 4) {
            float xv[8][4];
#pragma unroll
            for (int i = 0; i < 8; i++) {
                float4 t4 = *(const float4*)(xs + (r0 + i) * XS_STRIDE + k4);
                xv[i][0] = t4.x; xv[i][1] = t4.y; xv[i][2] = t4.z; xv[i][3] = t4.w;
            }
#pragma unroll
            for (int kk = 0; kk < 4; kk++) {
                float4 w4 = *(const float4*)(Ws + (kt + k4 + kk) * C_DIM + c0);
                unsigned long long wp[4];
                wp[0] = pack2(w4.x, w4.x);
                wp[1] = pack2(w4.y, w4.y);
                wp[2] = pack2(w4.z, w4.z);
                wp[3] = pack2(w4.w, w4.w);
#pragma unroll
                for (int p = 0; p < 4; p++) {
                    unsigned long long xp = pack2(xv[2 * p][kk], xv[2 * p + 1][kk]);
#pragma unroll
                    for (int j = 0; j < 4; j++) fma2(acc[p][j], xp, wp[j]);
                }
            }
        }
    }

    // Epilogue: g[row] = dis[row] * h[row]
#pragma unroll
    for (int p = 0; p < 4; p++) {
        int rA = base + r0 + 2 * p;
        int rB = rA + 1;
        float lo[4], hi[4];
#pragma unroll
        for (int j = 0; j < 4; j++) unpack2(acc[p][j], lo[j], hi[j]);
        if (rA < n) {
            float d = g_dis[rA];
            g_h[(size_t)rA * 16 + cg] =
                make_float4(d * lo[0], d * lo[1], d * lo[2], d * lo[3]);
        }
        if (rB < n) {
            float d = g_dis[rB];
            g_h[(size_t)rB * 16 + cg] =
                make_float4(d * hi[0], d * hi[1], d * hi[2], d * hi[3]);
        }
    }
}

// ---------------------------------------------------------------------------
// K5: scatter  out[col] += g[row]     (16 threads per edge, v4 reductions)
// ---------------------------------------------------------------------------
__global__ void scatter_kernel(const void* __restrict__ ei,
                               float* __restrict__ out, int E) {
    unsigned int tid = blockIdx.x * blockDim.x + threadIdx.x;
    int e = tid >> 4;
    int q = tid & 15;
    if (e >= E) return;
    int is64 = g_is64;
    int row = edge_at(ei, is64, (size_t)e);        // src
    int col = edge_at(ei, is64, (size_t)E + e);    // dst
    float4 v = __ldg(&g_h[(size_t)row * 16 + q]);
    float* dst = out + (size_t)col * C_DIM + q * 4;
    asm volatile("red.global.add.v4.f32 [%0], {%1, %2, %3, %4};"
                 :: "l"(dst), "f"(v.x), "f"(v.y), "f"(v.z), "f"(v.w)
                 : "memory");
}

// ---------------------------------------------------------------------------
// K6: out = dis * (acc + g) + b     (self-loop term h/deg = dis*g)
// ---------------------------------------------------------------------------
__global__ void final_kernel(float4* __restrict__ out4,
                             const float4* __restrict__ b4, int n) {
    int i = blockIdx.x * blockDim.x + threadIdx.x;
    if (i >= n * 16) return;
    int node = i >> 4;
    int q = i & 15;
    float d = g_dis[node];
    float4 a = out4[i];
    float4 g = g_h[i];
    float4 b = b4[q];
    float4 r;
    r.x = d * (a.x + g.x) + b.x;
    r.y = d * (a.y + g.y) + b.y;
    r.z = d * (a.z + g.z) + b.z;
    r.w = d * (a.w + g.w) + b.w;
    out4[i] = r;
}

// ---------------------------------------------------------------------------
extern "C" void kernel_launch(void* const* d_in, const int* in_sizes, int n_in,
                              void* d_out, int out_size) {
    const float* x = (const float*)d_in[0];
    const void* ei = d_in[1];
    const float* W = (const float*)d_in[2];
    const float* b = (const float*)d_in[3];
    float* out = (float*)d_out;

    int n = in_sizes[0] / K_DIM;   // 100000
    int E = in_sizes[1] / 2;       // 3200000

    const int T = 256;
    size_t gemm_smem = (size_t)(K_DIM * C_DIM + GM_TM * XS_STRIDE) * sizeof(float);
    cudaFuncSetAttribute(gemm_kernel, cudaFuncAttributeMaxDynamicSharedMemorySize,
                         (int)gemm_smem);

    int nt16 = n * 16;  // float4 count of out / g

    init_kernel<<<(nt16 + T - 1) / T, T>>>((float4*)out, n);
    detect_kernel<<<16, T>>>((const long long*)ei, E, n);
    deg_kernel<<<(E + T - 1) / T, T>>>(ei, E);
    dis_kernel<<<(n + T - 1) / T, T>>>(n);
    gemm_kernel<<<(n + GM_TM - 1) / GM_TM, T, gemm_smem>>>(x, W, n);
    {
        long long total = (long long)E * 16;
        int blocks = (int)((total + T - 1) / T);
        scatter_kernel<<<blocks, T>>>(ei, out, E);
    }
    final_kernel<<<(nt16 + T - 1) / T, T>>>((float4*)out, (const float4*)b, n);
}

// round 6
// speedup vs baseline: 1.4277x; 1.4277x over previous
#include <cuda_runtime.h>
#include <cstdint>

// Problem constants (shapes fixed by the dataset)
#define K_DIM 256
#define C_DIM 64
#define MAX_N 100000
#define MAX_E 3200000
#define SCAN_B 512   // nodes per scan block

// Scratch (no allocations allowed -> __device__ globals)
__device__ float4 g_h[(size_t)MAX_N * 16];     // g = dis[row] * (x @ W)  [N,64]
__device__ float  g_dis[MAX_N];                // deg^{-1/2}
__device__ int    g_cnt[MAX_N];                // in-degree (excl. self loop)
__device__ int    g_row_start[MAX_N + 1];      // CSR offsets (by dst)
__device__ int    g_cursor[MAX_N];             // fill cursors
__device__ int    g_csr_src[MAX_E];            // CSR column data: src per in-edge
__device__ int    g_part[1024];                // scan block partials
__device__ int    g_part_scan[1024];           // exclusive-scanned partials
__device__ int    g_is64;                      // edge_index dtype flag

// ---------------------------------------------------------------------------
// f32x2 packed-FMA helpers
// ---------------------------------------------------------------------------
__device__ __forceinline__ unsigned long long pack2(float lo, float hi) {
    unsigned long long r;
    asm("mov.b64 %0, {%1, %2};" : "=l"(r) : "f"(lo), "f"(hi));
    return r;
}
__device__ __forceinline__ void unpack2(unsigned long long v, float& lo, float& hi) {
    asm("mov.b64 {%0, %1}, %2;" : "=f"(lo), "=f"(hi) : "l"(v));
}
__device__ __forceinline__ void fma2(unsigned long long& d, unsigned long long a,
                                     unsigned long long b) {
    asm("fma.rn.f32x2 %0, %1, %2, %0;" : "+l"(d) : "l"(a), "l"(b));
}

// ---------------------------------------------------------------------------
// K0: init — zero counts, set dtype flag
// ---------------------------------------------------------------------------
__global__ void init_kernel(int n) {
    int i = blockIdx.x * blockDim.x + threadIdx.x;
    if (i < n) g_cnt[i] = 0;
    if (i == 0) g_is64 = 1;
}

// ---------------------------------------------------------------------------
// K1: detect edge_index dtype (int64 vs int32 aliasing heuristic)
// ---------------------------------------------------------------------------
__global__ void detect_kernel(const long long* __restrict__ ei, int E, int n) {
    int i = blockIdx.x * blockDim.x + threadIdx.x;
    int m = E < 4096 ? E : 4096;
    if (i < m) {
        long long v = ei[i];
        if (v < 0 || v >= (long long)n) g_is64 = 0;
    }
}

__device__ __forceinline__ int edge_at(const void* ei, int is64, size_t idx) {
    return is64 ? (int)((const long long*)ei)[idx] : ((const int*)ei)[idx];
}

// ---------------------------------------------------------------------------
// K2: count in-degree per destination node
// ---------------------------------------------------------------------------
__global__ void count_kernel(const void* __restrict__ ei, int E) {
    int e = blockIdx.x * blockDim.x + threadIdx.x;
    if (e >= E) return;
    int dst = edge_at(ei, g_is64, (size_t)E + e);
    atomicAdd(g_cnt + dst, 1);
}

// ---------------------------------------------------------------------------
// K3: per-block partial sums of counts
// ---------------------------------------------------------------------------
__global__ __launch_bounds__(SCAN_B) void scan_part_kernel(int n) {
    __shared__ int s[SCAN_B];
    int t = threadIdx.x;
    int i = blockIdx.x * SCAN_B + t;
    s[t] = (i < n) ? g_cnt[i] : 0;
    __syncthreads();
    for (int off = SCAN_B / 2; off > 0; off >>= 1) {
        if (t < off) s[t] += s[t + off];
        __syncthreads();
    }
    if (t == 0) g_part[blockIdx.x] = s[0];
}

// ---------------------------------------------------------------------------
// K4: exclusive scan of block partials (single block, up to 1024 partials)
// ---------------------------------------------------------------------------
__global__ __launch_bounds__(1024) void scan_partials_kernel(int nblocks) {
    __shared__ int s[1024];
    int t = threadIdx.x;
    int v = (t < nblocks) ? g_part[t] : 0;
    s[t] = v;
    __syncthreads();
    for (int off = 1; off < 1024; off <<= 1) {
        int x = (t >= off) ? s[t - off] : 0;
        __syncthreads();
        s[t] += x;
        __syncthreads();
    }
    if (t < nblocks) g_part_scan[t] = s[t] - v;  // exclusive
}

// ---------------------------------------------------------------------------
// K5: final scan — row_start, cursor, dis = rsqrt(cnt+1)
// ---------------------------------------------------------------------------
__global__ __launch_bounds__(SCAN_B) void scan_final_kernel(int n, int E) {
    __shared__ int s[SCAN_B];
    int t = threadIdx.x;
    int i = blockIdx.x * SCAN_B + t;
    int v = (i < n) ? g_cnt[i] : 0;
    s[t] = v;
    __syncthreads();
    for (int off = 1; off < SCAN_B; off <<= 1) {
        int x = (t >= off) ? s[t - off] : 0;
        __syncthreads();
        s[t] += x;
        __syncthreads();
    }
    if (i < n) {
        int start = g_part_scan[blockIdx.x] + s[t] - v;  // exclusive
        g_row_start[i] = start;
        g_cursor[i] = start;
        g_dis[i] = rsqrtf((float)(v + 1));
        if (i == n - 1) g_row_start[n] = E;
    }
}

// ---------------------------------------------------------------------------
// K6: fill CSR — csr_src[pos] = src, pos from per-dst cursor
// ---------------------------------------------------------------------------
__global__ void fill_kernel(const void* __restrict__ ei, int E) {
    int e = blockIdx.x * blockDim.x + threadIdx.x;
    if (e >= E) return;
    int is64 = g_is64;
    int src = edge_at(ei, is64, (size_t)e);
    int dst = edge_at(ei, is64, (size_t)E + e);
    int pos = atomicAdd(g_cursor + dst, 1);
    g_csr_src[pos] = src;
}

// ---------------------------------------------------------------------------
// K7: g = dis[row] * (x @ W)
// ---------------------------------------------------------------------------
#define GM_TM 128
#define GM_KT 32
#define XS_STRIDE 36

__global__ __launch_bounds__(256) void gemm_kernel(
    const float* __restrict__ x, const float* __restrict__ W, int n) {
    extern __shared__ float smem[];
    float* Ws = smem;                       // 256*64 floats = 64KB
    float* xs = smem + K_DIM * C_DIM;       // 128*36 floats = 18KB

    int t = threadIdx.x;
    int base = blockIdx.x * GM_TM;

    for (int i = t; i < (K_DIM * C_DIM) / 4; i += 256)
        ((float4*)Ws)[i] = ((const float4*)W)[i];

    int cg = t & 15;
    int rg = t >> 4;
    int c0 = cg * 4;
    int r0 = rg * 8;

    unsigned long long acc[4][4];
#pragma unroll
    for (int p = 0; p < 4; p++)
#pragma unroll
        for (int j = 0; j < 4; j++) acc[p][j] = 0ULL;

    for (int kt = 0; kt < K_DIM; kt += GM_KT) {
        __syncthreads();
        for (int i = t; i < (GM_TM * GM_KT) / 4; i += 256) {
            int row = i >> 3;
            int kq = i & 7;
            int grow = base + row;
            float4 v = make_float4(0.f, 0.f, 0.f, 0.f);
            if (grow < n)
                v = *(const float4*)(x + (size_t)grow * K_DIM + kt + kq * 4);
            *(float4*)(xs + row * XS_STRIDE + kq * 4) = v;
        }
        __syncthreads();

#pragma unroll
        for (int k4 = 0; k4 < GM_KT; k4 += 4) {
            float xv[8][4];
#pragma unroll
            for (int i = 0; i < 8; i++) {
                float4 t4 = *(const float4*)(xs + (r0 + i) * XS_STRIDE + k4);
                xv[i][0] = t4.x; xv[i][1] = t4.y; xv[i][2] = t4.z; xv[i][3] = t4.w;
            }
#pragma unroll
            for (int kk = 0; kk < 4; kk++) {
                float4 w4 = *(const float4*)(Ws + (kt + k4 + kk) * C_DIM + c0);
                unsigned long long wp[4];
                wp[0] = pack2(w4.x, w4.x);
                wp[1] = pack2(w4.y, w4.y);
                wp[2] = pack2(w4.z, w4.z);
                wp[3] = pack2(w4.w, w4.w);
#pragma unroll
                for (int p = 0; p < 4; p++) {
                    unsigned long long xp = pack2(xv[2 * p][kk], xv[2 * p + 1][kk]);
#pragma unroll
                    for (int j = 0; j < 4; j++) fma2(acc[p][j], xp, wp[j]);
                }
            }
        }
    }

#pragma unroll
    for (int p = 0; p < 4; p++) {
        int rA = base + r0 + 2 * p;
        int rB = rA + 1;
        float lo[4], hi[4];
#pragma unroll
        for (int j = 0; j < 4; j++) unpack2(acc[p][j], lo[j], hi[j]);
        if (rA < n) {
            float d = g_dis[rA];
            g_h[(size_t)rA * 16 + cg] =
                make_float4(d * lo[0], d * lo[1], d * lo[2], d * lo[3]);
        }
        if (rB < n) {
            float d = g_dis[rB];
            g_h[(size_t)rB * 16 + cg] =
                make_float4(d * hi[0], d * hi[1], d * hi[2], d * hi[3]);
        }
    }
}

// ---------------------------------------------------------------------------
// K8: gather + epilogue.  Warp per node; two half-warps split the edge list;
// 16 threads x float4 cover the 64-ch message. out = dis*(sum + g_self) + b.
// ---------------------------------------------------------------------------
__global__ __launch_bounds__(256) void gather_kernel(
    float4* __restrict__ out4, const float4* __restrict__ b4, int n) {
    int warp = (blockIdx.x * blockDim.x + threadIdx.x) >> 5;
    if (warp >= n) return;
    int lane = threadIdx.x & 31;
    int q = lane & 15;       // channel quad
    int sub = lane >> 4;     // half-warp id: edges j = start+sub, start+sub+2, ...

    int start = g_row_start[warp];
    int end = g_row_start[warp + 1];

    float ax = 0.f, ay = 0.f, az = 0.f, aw = 0.f;
#pragma unroll 2
    for (int j = start + sub; j < end; j += 2) {
        int src = __ldg(g_csr_src + j);
        float4 v = __ldg(&g_h[(size_t)src * 16 + q]);
        ax += v.x; ay += v.y; az += v.z; aw += v.w;
    }
    // combine the two half-warps (lane ^ 16 holds the partner partial)
    ax += __shfl_xor_sync(0xFFFFFFFFu, ax, 16);
    ay += __shfl_xor_sync(0xFFFFFFFFu, ay, 16);
    az += __shfl_xor_sync(0xFFFFFFFFu, az, 16);
    aw += __shfl_xor_sync(0xFFFFFFFFu, aw, 16);

    if (sub == 0) {
        float4 gs = g_h[(size_t)warp * 16 + q];  // self-loop term
        float d = g_dis[warp];
        float4 b = __ldg(b4 + q);
        float4 r;
        r.x = d * (ax + gs.x) + b.x;
        r.y = d * (ay + gs.y) + b.y;
        r.z = d * (az + gs.z) + b.z;
        r.w = d * (aw + gs.w) + b.w;
        out4[(size_t)warp * 16 + q] = r;
    }
}

// ---------------------------------------------------------------------------
extern "C" void kernel_launch(void* const* d_in, const int* in_sizes, int n_in,
                              void* d_out, int out_size) {
    const float* x = (const float*)d_in[0];
    const void* ei = d_in[1];
    const float* W = (const float*)d_in[2];
    const float* b = (const float*)d_in[3];
    float* out = (float*)d_out;

    int n = in_sizes[0] / K_DIM;   // 100000
    int E = in_sizes[1] / 2;       // 3200000

    const int T = 256;
    int scan_blocks = (n + SCAN_B - 1) / SCAN_B;  // 196

    size_t gemm_smem = (size_t)(K_DIM * C_DIM + GM_TM * XS_STRIDE) * sizeof(float);
    cudaFuncSetAttribute(gemm_kernel, cudaFuncAttributeMaxDynamicSharedMemorySize,
                         (int)gemm_smem);

    init_kernel<<<(n + T - 1) / T, T>>>(n);
    detect_kernel<<<16, T>>>((const long long*)ei, E, n);
    count_kernel<<<(E + T - 1) / T, T>>>(ei, E);
    scan_part_kernel<<<scan_blocks, SCAN_B>>>(n);
    scan_partials_kernel<<<1, 1024>>>(scan_blocks);
    scan_final_kernel<<<scan_blocks, SCAN_B>>>(n, E);
    fill_kernel<<<(E + T - 1) / T, T>>>(ei, E);
    gemm_kernel<<<(n + GM_TM - 1) / GM_TM, T, gemm_smem>>>(x, W, n);
    {
        long long total = (long long)n * 32;
        int blocks = (int)((total + T - 1) / T);
        gather_kernel<<<blocks, T>>>((float4*)out, (const float4*)b, n);
    }
}

// round 7
// speedup vs baseline: 1.4352x; 1.0053x over previous
#include <cuda_runtime.h>
#include <cuda_fp16.h>
#include <cstdint>

// Problem constants (shapes fixed by the dataset)
#define K_DIM 256
#define C_DIM 64
#define MAX_N 100000
#define MAX_E 3200000
#define SCAN_B 512   // nodes per scan block

// fp16 feature row: 64 ch * 2B = 128B = one L2 line
struct alignas(128) HRow { __half2 v[32]; };

// Scratch (no allocations allowed -> __device__ globals)
__device__ HRow  g_h2[MAX_N];                 // h = x @ W   (fp16, unscaled)
__device__ float g_dis[MAX_N];                // deg^{-1/2}
__device__ int   g_cnt[MAX_N];                // in-degree (excl. self loop)
__device__ int   g_row_start[MAX_N + 1];      // CSR offsets (by dst)
__device__ int   g_cursor[MAX_N];             // fill cursors
__device__ int   g_csr_src[MAX_E];            // CSR column data: src per in-edge
__device__ int   g_part[1024];                // scan block partials
__device__ int   g_part_scan[1024];           // exclusive-scanned partials
__device__ int   g_is64;                      // edge_index dtype flag

// ---------------------------------------------------------------------------
// f32x2 packed-FMA helpers
// ---------------------------------------------------------------------------
__device__ __forceinline__ unsigned long long pack2(float lo, float hi) {
    unsigned long long r;
    asm("mov.b64 %0, {%1, %2};" : "=l"(r) : "f"(lo), "f"(hi));
    return r;
}
__device__ __forceinline__ void unpack2(unsigned long long v, float& lo, float& hi) {
    asm("mov.b64 {%0, %1}, %2;" : "=f"(lo), "=f"(hi) : "l"(v));
}
__device__ __forceinline__ void fma2(unsigned long long& d, unsigned long long a,
                                     unsigned long long b) {
    asm("fma.rn.f32x2 %0, %1, %2, %0;" : "+l"(d) : "l"(a), "l"(b));
}

// ---------------------------------------------------------------------------
// K0: init — zero counts, set dtype flag
// ---------------------------------------------------------------------------
__global__ void init_kernel(int n) {
    int i = blockIdx.x * blockDim.x + threadIdx.x;
    if (i < n) g_cnt[i] = 0;
    if (i == 0) g_is64 = 1;
}

// ---------------------------------------------------------------------------
// K1: detect edge_index dtype (int64 vs int32 aliasing heuristic)
// ---------------------------------------------------------------------------
__global__ void detect_kernel(const long long* __restrict__ ei, int E, int n) {
    int i = blockIdx.x * blockDim.x + threadIdx.x;
    int m = E < 4096 ? E : 4096;
    if (i < m) {
        long long v = ei[i];
        if (v < 0 || v >= (long long)n) g_is64 = 0;
    }
}

__device__ __forceinline__ int edge_at(const void* ei, int is64, size_t idx) {
    return is64 ? (int)((const long long*)ei)[idx] : ((const int*)ei)[idx];
}

// ---------------------------------------------------------------------------
// K2: count in-degree per destination node
// ---------------------------------------------------------------------------
__global__ void count_kernel(const void* __restrict__ ei, int E) {
    int e = blockIdx.x * blockDim.x + threadIdx.x;
    if (e >= E) return;
    int dst = edge_at(ei, g_is64, (size_t)E + e);
    atomicAdd(g_cnt + dst, 1);
}

// ---------------------------------------------------------------------------
// K3: per-block partial sums of counts
// ---------------------------------------------------------------------------
__global__ __launch_bounds__(SCAN_B) void scan_part_kernel(int n) {
    __shared__ int s[SCAN_B];
    int t = threadIdx.x;
    int i = blockIdx.x * SCAN_B + t;
    s[t] = (i < n) ? g_cnt[i] : 0;
    __syncthreads();
    for (int off = SCAN_B / 2; off > 0; off >>= 1) {
        if (t < off) s[t] += s[t + off];
        __syncthreads();
    }
    if (t == 0) g_part[blockIdx.x] = s[0];
}

// ---------------------------------------------------------------------------
// K4: exclusive scan of block partials (single block)
// ---------------------------------------------------------------------------
__global__ __launch_bounds__(1024) void scan_partials_kernel(int nblocks) {
    __shared__ int s[1024];
    int t = threadIdx.x;
    int v = (t < nblocks) ? g_part[t] : 0;
    s[t] = v;
    __syncthreads();
    for (int off = 1; off < 1024; off <<= 1) {
        int x = (t >= off) ? s[t - off] : 0;
        __syncthreads();
        s[t] += x;
        __syncthreads();
    }
    if (t < nblocks) g_part_scan[t] = s[t] - v;  // exclusive
}

// ---------------------------------------------------------------------------
// K5: final scan — row_start, cursor, dis = rsqrt(cnt+1)
// ---------------------------------------------------------------------------
__global__ __launch_bounds__(SCAN_B) void scan_final_kernel(int n, int E) {
    __shared__ int s[SCAN_B];
    int t = threadIdx.x;
    int i = blockIdx.x * SCAN_B + t;
    int v = (i < n) ? g_cnt[i] : 0;
    s[t] = v;
    __syncthreads();
    for (int off = 1; off < SCAN_B; off <<= 1) {
        int x = (t >= off) ? s[t - off] : 0;
        __syncthreads();
        s[t] += x;
        __syncthreads();
    }
    if (i < n) {
        int start = g_part_scan[blockIdx.x] + s[t] - v;  // exclusive
        g_row_start[i] = start;
        g_cursor[i] = start;
        g_dis[i] = rsqrtf((float)(v + 1));
        if (i == n - 1) g_row_start[n] = E;
    }
}

// ---------------------------------------------------------------------------
// K6: fill CSR — csr_src[pos] = src, pos from per-dst cursor
// ---------------------------------------------------------------------------
__global__ void fill_kernel(const void* __restrict__ ei, int E) {
    int e = blockIdx.x * blockDim.x + threadIdx.x;
    if (e >= E) return;
    int is64 = g_is64;
    int src = edge_at(ei, is64, (size_t)e);
    int dst = edge_at(ei, is64, (size_t)E + e);
    int pos = atomicAdd(g_cursor + dst, 1);
    g_csr_src[pos] = src;
}

// ---------------------------------------------------------------------------
// K7: h = x @ W  -> fp16 rows (unscaled; dis applied in the gather)
// ---------------------------------------------------------------------------
#define GM_TM 128
#define GM_KT 32
#define XS_STRIDE 36

__global__ __launch_bounds__(256) void gemm_kernel(
    const float* __restrict__ x, const float* __restrict__ W, int n) {
    extern __shared__ float smem[];
    float* Ws = smem;                       // 256*64 floats = 64KB
    float* xs = smem + K_DIM * C_DIM;       // 128*36 floats = 18KB

    int t = threadIdx.x;
    int base = blockIdx.x * GM_TM;

    for (int i = t; i < (K_DIM * C_DIM) / 4; i += 256)
        ((float4*)Ws)[i] = ((const float4*)W)[i];

    int cg = t & 15;
    int rg = t >> 4;
    int c0 = cg * 4;
    int r0 = rg * 8;

    unsigned long long acc[4][4];
#pragma unroll
    for (int p = 0; p < 4; p++)
#pragma unroll
        for (int j = 0; j < 4; j++) acc[p][j] = 0ULL;

    for (int kt = 0; kt < K_DIM; kt += GM_KT) {
        __syncthreads();
        for (int i = t; i < (GM_TM * GM_KT) / 4; i += 256) {
            int row = i >> 3;
            int kq = i & 7;
            int grow = base + row;
            float4 v = make_float4(0.f, 0.f, 0.f, 0.f);
            if (grow < n)
                v = *(const float4*)(x + (size_t)grow * K_DIM + kt + kq * 4);
            *(float4*)(xs + row * XS_STRIDE + kq * 4) = v;
        }
        __syncthreads();

#pragma unroll
        for (int k4 = 0; k4 < GM_KT; k4 += 4) {
            float xv[8][4];
#pragma unroll
            for (int i = 0; i < 8; i++) {
                float4 t4 = *(const float4*)(xs + (r0 + i) * XS_STRIDE + k4);
                xv[i][0] = t4.x; xv[i][1] = t4.y; xv[i][2] = t4.z; xv[i][3] = t4.w;
            }
#pragma unroll
            for (int kk = 0; kk < 4; kk++) {
                float4 w4 = *(const float4*)(Ws + (kt + k4 + kk) * C_DIM + c0);
                unsigned long long wp[4];
                wp[0] = pack2(w4.x, w4.x);
                wp[1] = pack2(w4.y, w4.y);
                wp[2] = pack2(w4.z, w4.z);
                wp[3] = pack2(w4.w, w4.w);
#pragma unroll
                for (int p = 0; p < 4; p++) {
                    unsigned long long xp = pack2(xv[2 * p][kk], xv[2 * p + 1][kk]);
#pragma unroll
                    for (int j = 0; j < 4; j++) fma2(acc[p][j], xp, wp[j]);
                }
            }
        }
    }

#pragma unroll
    for (int p = 0; p < 4; p++) {
        int rA = base + r0 + 2 * p;
        int rB = rA + 1;
        float lo[4], hi[4];
#pragma unroll
        for (int j = 0; j < 4; j++) unpack2(acc[p][j], lo[j], hi[j]);
        if (rA < n) {
            __half2 a = __floats2half2_rn(lo[0], lo[1]);
            __half2 b = __floats2half2_rn(lo[2], lo[3]);
            uint2 u = make_uint2(*(unsigned*)&a, *(unsigned*)&b);
            ((uint2*)g_h2[rA].v)[cg] = u;
        }
        if (rB < n) {
            __half2 a = __floats2half2_rn(hi[0], hi[1]);
            __half2 b = __floats2half2_rn(hi[2], hi[3]);
            uint2 u = make_uint2(*(unsigned*)&a, *(unsigned*)&b);
            ((uint2*)g_h2[rB].v)[cg] = u;
        }
    }
}

// ---------------------------------------------------------------------------
// K8: gather + epilogue.  Warp per node; two half-warps split the edge list;
// 16 threads x 8B (4 fp16 ch) cover the 128B row = 1 L2 line per edge.
// out = dis_dst * (sum_e dis_src*h_src + dis_dst*h_dst) + b.
// ---------------------------------------------------------------------------
__global__ __launch_bounds__(256) void gather_kernel(
    float4* __restrict__ out4, const float4* __restrict__ b4, int n) {
    int warp = (blockIdx.x * blockDim.x + threadIdx.x) >> 5;
    if (warp >= n) return;
    int lane = threadIdx.x & 31;
    int q = lane & 15;       // channel quad (4 fp16 = 8B)
    int sub = lane >> 4;     // half-warp id

    int start = g_row_start[warp];
    int end = g_row_start[warp + 1];

    float ax = 0.f, ay = 0.f, az = 0.f, aw = 0.f;
#pragma unroll 2
    for (int j = start + sub; j < end; j += 2) {
        int src = __ldg(g_csr_src + j);
        float ds = __ldg(g_dis + src);
        uint2 u = __ldg((const uint2*)g_h2[src].v + q);
        float2 f01 = __half22float2(*(__half2*)&u.x);
        float2 f23 = __half22float2(*(__half2*)&u.y);
        ax = fmaf(ds, f01.x, ax);
        ay = fmaf(ds, f01.y, ay);
        az = fmaf(ds, f23.x, az);
        aw = fmaf(ds, f23.y, aw);
    }
    ax += __shfl_xor_sync(0xFFFFFFFFu, ax, 16);
    ay += __shfl_xor_sync(0xFFFFFFFFu, ay, 16);
    az += __shfl_xor_sync(0xFFFFFFFFu, az, 16);
    aw += __shfl_xor_sync(0xFFFFFFFFu, aw, 16);

    if (sub == 0) {
        float d = g_dis[warp];
        uint2 u = __ldg((const uint2*)g_h2[warp].v + q);   // self-loop term
        float2 s01 = __half22float2(*(__half2*)&u.x);
        float2 s23 = __half22float2(*(__half2*)&u.y);
        float4 b = __ldg(b4 + q);
        float4 r;
        r.x = fmaf(d, fmaf(d, s01.x, ax), b.x);
        r.y = fmaf(d, fmaf(d, s01.y, ay), b.y);
        r.z = fmaf(d, fmaf(d, s23.x, az), b.z);
        r.w = fmaf(d, fmaf(d, s23.y, aw), b.w);
        out4[(size_t)warp * 16 + q] = r;
    }
}

// ---------------------------------------------------------------------------
extern "C" void kernel_launch(void* const* d_in, const int* in_sizes, int n_in,
                              void* d_out, int out_size) {
    const float* x = (const float*)d_in[0];
    const void* ei = d_in[1];
    const float* W = (const float*)d_in[2];
    const float* b = (const float*)d_in[3];
    float* out = (float*)d_out;

    int n = in_sizes[0] / K_DIM;   // 100000
    int E = in_sizes[1] / 2;       // 3200000

    const int T = 256;
    int scan_blocks = (n + SCAN_B - 1) / SCAN_B;  // 196

    size_t gemm_smem = (size_t)(K_DIM * C_DIM + GM_TM * XS_STRIDE) * sizeof(float);
    cudaFuncSetAttribute(gemm_kernel, cudaFuncAttributeMaxDynamicSharedMemorySize,
                         (int)gemm_smem);

    init_kernel<<<(n + T - 1) / T, T>>>(n);
    detect_kernel<<<16, T>>>((const long long*)ei, E, n);
    count_kernel<<<(E + T - 1) / T, T>>>(ei, E);
    scan_part_kernel<<<scan_blocks, SCAN_B>>>(n);
    scan_partials_kernel<<<1, 1024>>>(scan_blocks);
    scan_final_kernel<<<scan_blocks, SCAN_B>>>(n, E);
    fill_kernel<<<(E + T - 1) / T, T>>>(ei, E);
    gemm_kernel<<<(n + GM_TM - 1) / GM_TM, T, gemm_smem>>>(x, W, n);
    {
        long long total = (long long)n * 32;
        int blocks = (int)((total + T - 1) / T);
        gather_kernel<<<blocks, T>>>((float4*)out, (const float4*)b, n);
    }
}

// round 8
// speedup vs baseline: 1.7364x; 1.2099x over previous
#include <cuda_runtime.h>
#include <cuda_fp16.h>
#include <cstdint>

// Problem constants (shapes fixed by the dataset)
#define K_DIM 256
#define C_DIM 64
#define MAX_N 100000
#define MAX_E 3200000
#define SCAN_B 512   // nodes per scan block

// fp16 feature row: 64 ch * 2B = 128B = one L2 line
struct alignas(128) HRow { __half2 v[32]; };

// Scratch (no allocations allowed -> __device__ globals)
__device__ HRow  g_h2[MAX_N];                 // h = x @ W (fp16); scaled to dis*h in-place
__device__ float g_dis[MAX_N];                // deg^{-1/2}
__device__ int   g_cnt[MAX_N];                // in-degree (excl. self loop)
__device__ int   g_row_start[MAX_N + 1];      // CSR offsets (by dst)
__device__ int   g_cursor[MAX_N];             // fill cursors
__device__ int   g_csr_src[MAX_E];            // CSR column data: src per in-edge
__device__ int   g_part[1024];                // scan block partials
__device__ int   g_part_scan[1024];           // exclusive-scanned partials
__device__ int   g_is64 = 1;                  // edge_index dtype flag (sticky, deterministic)

// ---------------------------------------------------------------------------
// f32x2 packed-FMA helpers
// ---------------------------------------------------------------------------
__device__ __forceinline__ unsigned long long pack2(float lo, float hi) {
    unsigned long long r;
    asm("mov.b64 %0, {%1, %2};" : "=l"(r) : "f"(lo), "f"(hi));
    return r;
}
__device__ __forceinline__ void unpack2(unsigned long long v, float& lo, float& hi) {
    asm("mov.b64 {%0, %1}, %2;" : "=f"(lo), "=f"(hi) : "l"(v));
}
__device__ __forceinline__ void fma2(unsigned long long& d, unsigned long long a,
                                     unsigned long long b) {
    asm("fma.rn.f32x2 %0, %1, %2, %0;" : "+l"(d) : "l"(a), "l"(b));
}

// ---------------------------------------------------------------------------
// K0: init counts + dtype detection (int64 vs int32 aliasing heuristic).
// Detection only clears the flag; result is identical every call.
// ---------------------------------------------------------------------------
__global__ void init_detect_kernel(const long long* __restrict__ ei, int E, int n) {
    int i = blockIdx.x * blockDim.x + threadIdx.x;
    if (i < n) g_cnt[i] = 0;
    int m = E < 4096 ? E : 4096;
    if (i < m) {
        long long v = ei[i];
        if (v < 0 || v >= (long long)n) g_is64 = 0;
    }
}

__device__ __forceinline__ int edge_at(const void* ei, int is64, size_t idx) {
    return is64 ? (int)((const long long*)ei)[idx] : ((const int*)ei)[idx];
}

// ---------------------------------------------------------------------------
// K1: count in-degree per destination node
// ---------------------------------------------------------------------------
__global__ void count_kernel(const void* __restrict__ ei, int E) {
    int e = blockIdx.x * blockDim.x + threadIdx.x;
    if (e >= E) return;
    int dst = edge_at(ei, g_is64, (size_t)E + e);
    atomicAdd(g_cnt + dst, 1);
}

// ---------------------------------------------------------------------------
// K2: per-block partial sums of counts
// ---------------------------------------------------------------------------
__global__ __launch_bounds__(SCAN_B) void scan_part_kernel(int n) {
    __shared__ int s[SCAN_B];
    int t = threadIdx.x;
    int i = blockIdx.x * SCAN_B + t;
    s[t] = (i < n) ? g_cnt[i] : 0;
    __syncthreads();
    for (int off = SCAN_B / 2; off > 0; off >>= 1) {
        if (t < off) s[t] += s[t + off];
        __syncthreads();
    }
    if (t == 0) g_part[blockIdx.x] = s[0];
}

// ---------------------------------------------------------------------------
// K3: exclusive scan of block partials (single block)
// ---------------------------------------------------------------------------
__global__ __launch_bounds__(1024) void scan_partials_kernel(int nblocks) {
    __shared__ int s[1024];
    int t = threadIdx.x;
    int v = (t < nblocks) ? g_part[t] : 0;
    s[t] = v;
    __syncthreads();
    for (int off = 1; off < 1024; off <<= 1) {
        int x = (t >= off) ? s[t - off] : 0;
        __syncthreads();
        s[t] += x;
        __syncthreads();
    }
    if (t < nblocks) g_part_scan[t] = s[t] - v;  // exclusive
}

// ---------------------------------------------------------------------------
// K4: final scan — row_start, cursor, dis = rsqrt(cnt+1)
// ---------------------------------------------------------------------------
__global__ __launch_bounds__(SCAN_B) void scan_final_kernel(int n, int E) {
    __shared__ int s[SCAN_B];
    int t = threadIdx.x;
    int i = blockIdx.x * SCAN_B + t;
    int v = (i < n) ? g_cnt[i] : 0;
    s[t] = v;
    __syncthreads();
    for (int off = 1; off < SCAN_B; off <<= 1) {
        int x = (t >= off) ? s[t - off] : 0;
        __syncthreads();
        s[t] += x;
        __syncthreads();
    }
    if (i < n) {
        int start = g_part_scan[blockIdx.x] + s[t] - v;  // exclusive
        g_row_start[i] = start;
        g_cursor[i] = start;
        g_dis[i] = rsqrtf((float)(v + 1));
        if (i == n - 1) g_row_start[n] = E;
    }
}

// ---------------------------------------------------------------------------
// K5: fill CSR — csr_src[pos] = src, pos from per-dst cursor
// ---------------------------------------------------------------------------
__global__ void fill_kernel(const void* __restrict__ ei, int E) {
    int e = blockIdx.x * blockDim.x + threadIdx.x;
    if (e >= E) return;
    int is64 = g_is64;
    int src = edge_at(ei, is64, (size_t)e);
    int dst = edge_at(ei, is64, (size_t)E + e);
    int pos = atomicAdd(g_cursor + dst, 1);
    g_csr_src[pos] = src;
}

// ---------------------------------------------------------------------------
// K6 (parallel stream): h = x @ W -> fp16 rows (unscaled)
// ---------------------------------------------------------------------------
#define GM_TM 128
#define GM_KT 32
#define XS_STRIDE 36

__global__ __launch_bounds__(256) void gemm_kernel(
    const float* __restrict__ x, const float* __restrict__ W, int n) {
    extern __shared__ float smem[];
    float* Ws = smem;                       // 256*64 floats = 64KB
    float* xs = smem + K_DIM * C_DIM;       // 128*36 floats = 18KB

    int t = threadIdx.x;
    int base = blockIdx.x * GM_TM;

    for (int i = t; i < (K_DIM * C_DIM) / 4; i += 256)
        ((float4*)Ws)[i] = ((const float4*)W)[i];

    int cg = t & 15;
    int rg = t >> 4;
    int c0 = cg * 4;
    int r0 = rg * 8;

    unsigned long long acc[4][4];
#pragma unroll
    for (int p = 0; p < 4; p++)
#pragma unroll
        for (int j = 0; j < 4; j++) acc[p][j] = 0ULL;

    for (int kt = 0; kt < K_DIM; kt += GM_KT) {
        __syncthreads();
        for (int i = t; i < (GM_TM * GM_KT) / 4; i += 256) {
            int row = i >> 3;
            int kq = i & 7;
            int grow = base + row;
            float4 v = make_float4(0.f, 0.f, 0.f, 0.f);
            if (grow < n)
                v = *(const float4*)(x + (size_t)grow * K_DIM + kt + kq * 4);
            *(float4*)(xs + row * XS_STRIDE + kq * 4) = v;
        }
        __syncthreads();

#pragma unroll
        for (int k4 = 0; k4 < GM_KT; k4 += 4) {
            float xv[8][4];
#pragma unroll
            for (int i = 0; i < 8; i++) {
                float4 t4 = *(const float4*)(xs + (r0 + i) * XS_STRIDE + k4);
                xv[i][0] = t4.x; xv[i][1] = t4.y; xv[i][2] = t4.z; xv[i][3] = t4.w;
            }
#pragma unroll
            for (int kk = 0; kk < 4; kk++) {
                float4 w4 = *(const float4*)(Ws + (kt + k4 + kk) * C_DIM + c0);
                unsigned long long wp[4];
                wp[0] = pack2(w4.x, w4.x);
                wp[1] = pack2(w4.y, w4.y);
                wp[2] = pack2(w4.z, w4.z);
                wp[3] = pack2(w4.w, w4.w);
#pragma unroll
                for (int p = 0; p < 4; p++) {
                    unsigned long long xp = pack2(xv[2 * p][kk], xv[2 * p + 1][kk]);
#pragma unroll
                    for (int j = 0; j < 4; j++) fma2(acc[p][j], xp, wp[j]);
                }
            }
        }
    }

#pragma unroll
    for (int p = 0; p < 4; p++) {
        int rA = base + r0 + 2 * p;
        int rB = rA + 1;
        float lo[4], hi[4];
#pragma unroll
        for (int j = 0; j < 4; j++) unpack2(acc[p][j], lo[j], hi[j]);
        if (rA < n) {
            __half2 a = __floats2half2_rn(lo[0], lo[1]);
            __half2 b = __floats2half2_rn(lo[2], lo[3]);
            uint2 u = make_uint2(*(unsigned*)&a, *(unsigned*)&b);
            ((uint2*)g_h2[rA].v)[cg] = u;
        }
        if (rB < n) {
            __half2 a = __floats2half2_rn(hi[0], hi[1]);
            __half2 b = __floats2half2_rn(hi[2], hi[3]);
            uint2 u = make_uint2(*(unsigned*)&a, *(unsigned*)&b);
            ((uint2*)g_h2[rB].v)[cg] = u;
        }
    }
}

// ---------------------------------------------------------------------------
// K7: scale rows in place: g = dis * h   (runs after GEMM join + scan_final)
// One thread per 16B chunk (8 fp16 channels); n*8 threads total.
// ---------------------------------------------------------------------------
__global__ void scale_kernel(int n) {
    int i = blockIdx.x * blockDim.x + threadIdx.x;
    if (i >= n * 8) return;
    int node = i >> 3;
    float d = g_dis[node];
    uint4* p = (uint4*)g_h2 + i;
    uint4 u = *p;
    __half2* h = (__half2*)&u;
#pragma unroll
    for (int k = 0; k < 4; k++) {
        float2 f = __half22float2(h[k]);
        h[k] = __floats2half2_rn(d * f.x, d * f.y);
    }
    *p = u;
}

// ---------------------------------------------------------------------------
// K8: gather + epilogue. Warp per node; 4 edges in flight (8 lanes x 16B
// each = full 128B row per edge). out = dis_dst*(sum + g_self) + b.
// ---------------------------------------------------------------------------
__global__ __launch_bounds__(256) void gather_kernel(
    float4* __restrict__ out4, const float4* __restrict__ b4, int n) {
    int warp = (blockIdx.x * blockDim.x + threadIdx.x) >> 5;
    if (warp >= n) return;
    int lane = threadIdx.x & 31;
    int q = lane & 7;        // 16B chunk: channels [q*8, q*8+8)
    int sub = lane >> 3;     // 0..3: edge slot

    int start = g_row_start[warp];
    int end = g_row_start[warp + 1];

    float a[8] = {0.f, 0.f, 0.f, 0.f, 0.f, 0.f, 0.f, 0.f};
#pragma unroll 2
    for (int j = start + sub; j < end; j += 4) {
        int src = __ldg(g_csr_src + j);
        uint4 u = __ldg((const uint4*)g_h2[src].v + q);
        __half2* h = (__half2*)&u;
#pragma unroll
        for (int k = 0; k < 4; k++) {
            float2 f = __half22float2(h[k]);
            a[2 * k] += f.x;
            a[2 * k + 1] += f.y;
        }
    }
    // reduce the 4 edge slots (lanes q, q+8, q+16, q+24)
#pragma unroll
    for (int k = 0; k < 8; k++) {
        a[k] += __shfl_xor_sync(0xFFFFFFFFu, a[k], 8);
        a[k] += __shfl_xor_sync(0xFFFFFFFFu, a[k], 16);
    }

    if (sub == 0) {
        float d = g_dis[warp];
        uint4 us = __ldg((const uint4*)g_h2[warp].v + q);  // self term (scaled)
        __half2* hs = (__half2*)&us;
        float4 b0 = __ldg(b4 + q * 2);
        float4 b1 = __ldg(b4 + q * 2 + 1);
        float s[8];
#pragma unroll
        for (int k = 0; k < 4; k++) {
            float2 f = __half22float2(hs[k]);
            s[2 * k] = f.x;
            s[2 * k + 1] = f.y;
        }
        float4 r0, r1;
        r0.x = fmaf(d, a[0] + s[0], b0.x);
        r0.y = fmaf(d, a[1] + s[1], b0.y);
        r0.z = fmaf(d, a[2] + s[2], b0.z);
        r0.w = fmaf(d, a[3] + s[3], b0.w);
        r1.x = fmaf(d, a[4] + s[4], b1.x);
        r1.y = fmaf(d, a[5] + s[5], b1.y);
        r1.z = fmaf(d, a[6] + s[6], b1.z);
        r1.w = fmaf(d, a[7] + s[7], b1.w);
        out4[(size_t)warp * 16 + q * 2] = r0;
        out4[(size_t)warp * 16 + q * 2 + 1] = r1;
    }
}

// ---------------------------------------------------------------------------
extern "C" void kernel_launch(void* const* d_in, const int* in_sizes, int n_in,
                              void* d_out, int out_size) {
    const float* x = (const float*)d_in[0];
    const void* ei = d_in[1];
    const float* W = (const float*)d_in[2];
    const float* b = (const float*)d_in[3];
    float* out = (float*)d_out;

    int n = in_sizes[0] / K_DIM;   // 100000
    int E = in_sizes[1] / 2;       // 3200000

    const int T = 256;
    int scan_blocks = (n + SCAN_B - 1) / SCAN_B;  // 196

    size_t gemm_smem = (size_t)(K_DIM * C_DIM + GM_TM * XS_STRIDE) * sizeof(float);
    cudaFuncSetAttribute(gemm_kernel, cudaFuncAttributeMaxDynamicSharedMemorySize,
                         (int)gemm_smem);

    // One-time stream/event creation (first call = uncaptured correctness run;
    // identical launch graph every call afterwards).
    static cudaStream_t s2 = nullptr;
    static cudaEvent_t evF = nullptr, evJ = nullptr;
    if (s2 == nullptr) {
        cudaStreamCreateWithFlags(&s2, cudaStreamNonBlocking);
        cudaEventCreateWithFlags(&evF, cudaEventDisableTiming);
        cudaEventCreateWithFlags(&evJ, cudaEventDisableTiming);
    }

    // Fork: GEMM on s2, CSR build on the main stream.
    cudaEventRecord(evF, 0);
    cudaStreamWaitEvent(s2, evF, 0);
    gemm_kernel<<<(n + GM_TM - 1) / GM_TM, T, gemm_smem, s2>>>(x, W, n);
    cudaEventRecord(evJ, s2);

    init_detect_kernel<<<(n + T - 1) / T, T>>>((const long long*)ei, E, n);
    count_kernel<<<(E + T - 1) / T, T>>>(ei, E);
    scan_part_kernel<<<scan_blocks, SCAN_B>>>(n);
    scan_partials_kernel<<<1, 1024>>>(scan_blocks);
    scan_final_kernel<<<scan_blocks, SCAN_B>>>(n, E);
    fill_kernel<<<(E + T - 1) / T, T>>>(ei, E);

    // Join: need h (GEMM) + dis (scan_final) before scaling.
    cudaStreamWaitEvent(0, evJ, 0);
    scale_kernel<<<(n * 8 + T - 1) / T, T>>>(n);
    {
        long long total = (long long)n * 32;
        int blocks = (int)((total + T - 1) / T);
        gather_kernel<<<blocks, T>>>((float4*)out, (const float4*)b, n);
    }
}